// round 1
// baseline (speedup 1.0000x reference)
#include <cuda_runtime.h>
#include <math.h>

#define D_MODEL 128
#define D_STATE 64
#define LSEQ    1024
#define BATCH   32

// Scratch (static device globals: allocation-free per harness rules)
__device__ float g_Krev[D_MODEL * LSEQ];                 // K reversed in time
__device__ float g_act [BATCH * D_MODEL * LSEQ];         // post-GELU activations (16 MB)

// ---------------------------------------------------------------------------
// Kernel A: K[d,l] = Re( sum_n C_n * (A_bar-1)/A * B_n * exp(A*dt*l) )
// stored reversed: g_Krev[d][1023-l] = K[d][l]
// ---------------------------------------------------------------------------
__global__ void k_genK(const float* __restrict__ log_dt,
                       const float* __restrict__ log_A_real,
                       const float* __restrict__ A_imag,
                       const float* __restrict__ B_re, const float* __restrict__ B_im,
                       const float* __restrict__ C_re, const float* __restrict__ C_im)
{
    const int d = blockIdx.x;
    __shared__ float arS[64], aiS[64], grS[64], giS[64];
    const int tid = threadIdx.x;

    const double INV2PI = 0.15915494309189535;
    const double TWOPI  = 6.283185307179586;

    if (tid < 64) {
        int n = tid;
        float dtv = expf(log_dt[d]);
        float Ar  = -expf(log_A_real[d * 64 + n]);
        float Ai  = A_imag[d * 64 + n];
        float ar  = Ar * dtv;
        float ai  = Ai * dtv;
        // A_bar = exp(ar + i*ai), accurate reduction for the phase
        double aid = (double)ai;
        float r0 = (float)(aid - rint(aid * INV2PI) * TWOPI);
        float s, c;
        __sincosf(r0, &s, &c);
        float e   = expf(ar);
        float Abr = e * c, Abi = e * s;
        // B_bar = (A_bar - 1)/A * B
        float nr = Abr - 1.0f, ni = Abi;
        float inv = 1.0f / (Ar * Ar + Ai * Ai);
        float br = (nr * Ar + ni * Ai) * inv;
        float bi = (ni * Ar - nr * Ai) * inv;
        float Br = B_re[d * 64 + n], Bi = B_im[d * 64 + n];
        float tr = br * Br - bi * Bi;
        float ti = br * Bi + bi * Br;
        // g = C * B_bar
        float Cr = C_re[d * 64 + n], Ci = C_im[d * 64 + n];
        grS[n] = Cr * tr - Ci * ti;
        giS[n] = Cr * ti + Ci * tr;
        arS[n] = ar;
        aiS[n] = ai;
    }
    __syncthreads();

    for (int l = tid; l < LSEQ; l += blockDim.x) {
        float lf = (float)l;
        float acc = 0.0f;
        #pragma unroll 4
        for (int n = 0; n < 64; n++) {
            float ph = aiS[n] * lf;                    // fp32 phase (matches reference rounding)
            double phd = (double)ph;
            float r = (float)(phd - rint(phd * INV2PI) * TWOPI);  // exact mod-2pi of ph
            float s, c;
            __sincosf(r, &s, &c);
            float e = __expf(arS[n] * lf);
            acc += e * (grS[n] * c - giS[n] * s);
        }
        g_Krev[d * LSEQ + (LSEQ - 1 - l)] = acc;
    }
}

// ---------------------------------------------------------------------------
// Kernel B: depthwise causal conv with REVERSED kernel + skip + Cheb-GELU
//   y[l] = sum_{t=0}^{l} Krev[t] * u[l-t];   g = cheb(y + u*D[d])
// One block per (b,d). 128 threads, 8 l's each, 8x8 register tile.
// ---------------------------------------------------------------------------
__global__ void __launch_bounds__(128) k_conv(const float* __restrict__ u,
                                              const float* __restrict__ Dvec)
{
    __shared__ __align__(16) float us[2 * LSEQ];   // [0,1024) zeros, [1024,2048) = u row
    __shared__ __align__(16) float Ks[LSEQ];

    const int d = blockIdx.x & (D_MODEL - 1);
    const int b = blockIdx.x >> 7;
    const int tid = threadIdx.x;

    const float* urow = u + (size_t)(b * D_MODEL + d) * LSEQ;
    const float* krow = g_Krev + d * LSEQ;
    for (int i = tid; i < LSEQ; i += 128) {
        us[i]        = 0.0f;
        us[LSEQ + i] = urow[i];
        Ks[i]        = krow[i];
    }
    __syncthreads();

    const int l0 = tid * 8;
    float y[8];
    #pragma unroll
    for (int j = 0; j < 8; j++) y[j] = 0.0f;

    for (int t = 0; t <= l0; t += 8) {
        float4 k0 = *(const float4*)&Ks[t];
        float4 k1 = *(const float4*)&Ks[t + 4];
        int base = LSEQ + l0 - t - 8;
        float4 u0 = *(const float4*)&us[base];
        float4 u1 = *(const float4*)&us[base + 4];
        float4 u2 = *(const float4*)&us[base + 8];
        float4 u3 = *(const float4*)&us[base + 12];
        float kk[8] = {k0.x, k0.y, k0.z, k0.w, k1.x, k1.y, k1.z, k1.w};
        float uu[16] = {u0.x, u0.y, u0.z, u0.w, u1.x, u1.y, u1.z, u1.w,
                        u2.x, u2.y, u2.z, u2.w, u3.x, u3.y, u3.z, u3.w};
        #pragma unroll
        for (int s = 0; s < 8; s++)
            #pragma unroll
            for (int j = 0; j < 8; j++)
                y[j] = fmaf(kk[s], uu[8 + j - s], y[j]);   // zero padding handles t > l
    }

    // skip + Chebyshev GELU (degree 6, domain [-5,15])
    const float Dd = Dvec[d];
    float* gout = g_act + (size_t)(b * D_MODEL + d) * LSEQ + l0;
    const float cc[5] = {1.371512430522f, -0.740775295685f, 0.134773988002f,
                         0.126019270103f, -0.239569101196f};
    #pragma unroll
    for (int j = 0; j < 8; j++) {
        float x = y[j] + us[LSEQ + l0 + j] * Dd;
        float t = (2.0f * x - 10.0f) * 0.05f;     // (2x-(hi+lo))/(hi-lo)
        float t0 = 1.0f, t1 = t;
        float res = 6.04831644882f + 8.094460228971f * t;
        #pragma unroll
        for (int i = 0; i < 5; i++) {
            float ti = 2.0f * t * t1 - t0;
            res += cc[i] * ti;
            t0 = t1; t1 = ti;
        }
        gout[j] = res;
    }
}

// ---------------------------------------------------------------------------
// Kernel C: GLU GEMM + gate + Wdec-weighted mean pool
//   a = W1[:128]@g + b1a ; bb = W1[128:]@g + b1b ; gate = clip(.25bb+.5,0,1)
//   out[b] += sum_{o,l} Wdec[o]*a*gate / 1024
// Block = (lchunk of 256, b). Dynamic smem: W1 transposed [128][260] + g tile.
// ---------------------------------------------------------------------------
__global__ void __launch_bounds__(256) k_head(const float* __restrict__ W1,
                                              const float* __restrict__ b1,
                                              const float* __restrict__ Wdec,
                                              float* __restrict__ out)
{
    extern __shared__ float smem[];
    float* W1T = smem;                    // 128 rows (d) x 260 (o, padded)
    float* gsh = smem + 128 * 260;        // 128 rows (d) x 36 (l, padded)

    const int tid = threadIdx.x;
    const int b   = blockIdx.y;

    // coalesced read of W1 [256][128], transposed store
    for (int idx = tid; idx < 256 * 128; idx += 256) {
        int o = idx >> 7, dd = idx & 127;
        W1T[dd * 260 + o] = W1[idx];
    }

    const int o0 = (tid >> 3) * 4;   // 0..124
    const int lg = tid & 7;          // 0..7  -> l sub-offsets lg*4..lg*4+3
    float b1a[4], b1b[4], wd[4];
    #pragma unroll
    for (int i = 0; i < 4; i++) {
        b1a[i] = b1[o0 + i];
        b1b[i] = b1[o0 + i + 128];
        wd[i]  = Wdec[o0 + i];
    }

    float partial = 0.0f;
    const float* gbase = g_act + (size_t)b * D_MODEL * LSEQ + blockIdx.x * 256;

    for (int sub = 0; sub < 8; sub++) {
        __syncthreads();   // also orders W1T writes before first GEMM
        const float* gsrc = gbase + sub * 32;
        for (int idx = tid; idx < 128 * 32; idx += 256) {
            int dd = idx >> 5, ll = idx & 31;
            gsh[dd * 36 + ll] = gsrc[dd * 1024 + ll];
        }
        __syncthreads();

        float accA[4][4], accB[4][4];
        #pragma unroll
        for (int i = 0; i < 4; i++)
            #pragma unroll
            for (int j = 0; j < 4; j++) { accA[i][j] = 0.0f; accB[i][j] = 0.0f; }

        #pragma unroll 2
        for (int dd = 0; dd < 128; dd++) {
            float4 g4 = *(const float4*)&gsh[dd * 36 + lg * 4];
            float4 wa = *(const float4*)&W1T[dd * 260 + o0];
            float4 wb = *(const float4*)&W1T[dd * 260 + o0 + 128];
            float gg[4]  = {g4.x, g4.y, g4.z, g4.w};
            float wav[4] = {wa.x, wa.y, wa.z, wa.w};
            float wbv[4] = {wb.x, wb.y, wb.z, wb.w};
            #pragma unroll
            for (int oi = 0; oi < 4; oi++)
                #pragma unroll
                for (int li = 0; li < 4; li++) {
                    accA[oi][li] = fmaf(wav[oi], gg[li], accA[oi][li]);
                    accB[oi][li] = fmaf(wbv[oi], gg[li], accB[oi][li]);
                }
        }

        #pragma unroll
        for (int oi = 0; oi < 4; oi++)
            #pragma unroll
            for (int li = 0; li < 4; li++) {
                float a    = accA[oi][li] + b1a[oi];
                float bb   = accB[oi][li] + b1b[oi];
                float gate = fminf(fmaxf(0.25f * bb + 0.5f, 0.0f), 1.0f);
                partial += wd[oi] * (a * gate);
            }
    }

    __shared__ float red[256];
    red[tid] = partial;
    __syncthreads();
    for (int s = 128; s > 0; s >>= 1) {
        if (tid < s) red[tid] += red[tid + s];
        __syncthreads();
    }
    if (tid == 0) atomicAdd(out + b, red[0] * (1.0f / 1024.0f));
}

__global__ void k_init(float* out, const float* __restrict__ bdec)
{
    int i = threadIdx.x;
    if (i < BATCH) out[i] = bdec[0];
}

// ---------------------------------------------------------------------------
extern "C" void kernel_launch(void* const* d_in, const int* in_sizes, int n_in,
                              void* d_out, int out_size)
{
    const float* u          = (const float*)d_in[0];
    const float* log_dt     = (const float*)d_in[1];
    const float* log_A_real = (const float*)d_in[2];
    const float* A_imag     = (const float*)d_in[3];
    const float* B_re       = (const float*)d_in[4];
    const float* B_im       = (const float*)d_in[5];
    const float* C_re       = (const float*)d_in[6];
    const float* C_im       = (const float*)d_in[7];
    const float* Dvec       = (const float*)d_in[8];
    const float* W1         = (const float*)d_in[9];
    const float* b1         = (const float*)d_in[10];
    const float* Wdec       = (const float*)d_in[11];
    const float* bdec       = (const float*)d_in[12];
    float* out = (float*)d_out;

    const int smemC = (128 * 260 + 128 * 36) * (int)sizeof(float);   // 151552 B
    cudaFuncSetAttribute(k_head, cudaFuncAttributeMaxDynamicSharedMemorySize, smemC);

    k_init<<<1, 32>>>(out, bdec);
    k_genK<<<D_MODEL, 256>>>(log_dt, log_A_real, A_imag, B_re, B_im, C_re, C_im);
    k_conv<<<BATCH * D_MODEL, 128>>>(u, Dvec);
    k_head<<<dim3(4, BATCH), 256, smemC>>>(W1, b1, Wdec, out);
}